// round 15
// baseline (speedup 1.0000x reference)
#include <cuda_runtime.h>
#include <cuda_bf16.h>

#define DIM   4096
#define NBLK  256          // 256 blocks * 16 warps = 4096 rows
#define NTHR  512

// ---------------- scratch (no allocations allowed) ----------------
__device__ float g_partE [NBLK];
__device__ float g_partE2[NBLK];
__device__ int   g_count = 0;

// Single fused kernel:
//  1) every block rebuilds psi[4096] in smem via MPS prefix/suffix split
//     psi[hi*64+lo] = sum_a L[hi][a] * R[lo][a]
//  2) 16 warps x 1 row each: acc = H[row] . psi  (one pass over H)
//     e_num  += psi[r]*acc ; e2_num += acc*acc   (H symmetric => <psi|H^2|psi> = |H psi|^2)
//  3) last block (atomic counter) reduces the 256 partials, computes norm from
//     its own psi copy (bitwise identical in all blocks), writes [energy, var],
//     resets counter.
__global__ __launch_bounds__(NTHR) void vqe_fused_kernel(
        const float* __restrict__ core0,   // (2,8)
        const float* __restrict__ mid,     // (10,8,2,8)
        const float* __restrict__ last,    // (8,2)
        const float* __restrict__ H,       // (4096,4096)
        float* __restrict__ out)
{
    __shared__ float sco[16 + 1280 + 16];        // core0 | mid | last
    __shared__ float LA[512], LB[512], RA[512], RB[512];
    __shared__ float spsi[DIM];                  // 16 KB
    __shared__ float rA[16], rB[16], rC[16];
    __shared__ int   s_is_last;

    const int tid = threadIdx.x;

    // ---- stage tiny cores into smem ----
    for (int i = tid; i < 16; i += NTHR) { sco[i] = core0[i]; sco[16 + 1280 + i] = last[i]; }
    for (int i = tid; i < 1280; i += NTHR) sco[16 + i] = mid[i];
    __syncthreads();
    const float* smid  = sco + 16;
    const float* slst  = sco + 16 + 1280;

    // ---- seed L^(0) (2 vectors = core0 rows), R^(0) (2 vectors from last) ----
    if (tid < 16) LA[tid] = sco[tid];                       // L0[s0*8+a] = core0[s0,a]
    if (tid >= 32 && tid < 48) {
        int t = tid - 32, p = t >> 3, a = t & 7;
        RA[p * 8 + a] = slst[a * 2 + p];                    // R0[p11][a] = last[a,p11]
    }
    __syncthreads();

    // ---- 5 doubling steps each side (L uses mid[0..4], R uses mid[9..5]) ----
    float *Lc = LA, *Ln = LB, *Rc = RA, *Rn = RB;
    int cnt = 2;
    for (int step = 0; step < 5; step++) {
        const int   tot = cnt * 16;                         // outputs per side
        const float* cl = smid + step * 128;
        const float* cr = smid + (9 - step) * 128;
        for (int idx = tid; idx < 2 * tot; idx += NTHR) {
            if (idx < tot) {                                // L: [s,p](b)
                const int b = idx & 7, sp = idx >> 3, p = sp & 1, s = sp >> 1;
                float sum = 0.f;
                #pragma unroll
                for (int a = 0; a < 8; a++)
                    sum = fmaf(Lc[s * 8 + a], cl[(a * 2 + p) * 8 + b], sum);
                Ln[idx] = sum;
            } else {                                        // R: [p,old](a), p = new MSB
                const int k = idx - tot;
                const int a = k & 7, v = k >> 3;
                const int p = (v >= cnt) ? 1 : 0;
                const int old = v - p * cnt;
                float sum = 0.f;
                #pragma unroll
                for (int b = 0; b < 8; b++)
                    sum = fmaf(cr[(a * 2 + p) * 8 + b], Rc[old * 8 + b], sum);
                Rn[k] = sum;
            }
        }
        __syncthreads();
        float* t;
        t = Lc; Lc = Ln; Ln = t;
        t = Rc; Rc = Rn; Rn = t;
        cnt <<= 1;
    }

    // ---- psi = outer contraction L[64][8] x R[64][8] ----
    for (int idx = tid; idx < DIM; idx += NTHR) {
        const int hi = idx >> 6, lo = idx & 63;
        float s = 0.f;
        #pragma unroll
        for (int a = 0; a < 8; a++)
            s = fmaf(Lc[hi * 8 + a], Rc[lo * 8 + a], s);
        spsi[idx] = s;
    }
    __syncthreads();

    // ---- matvec: one warp per row, float4 loads, warp-shuffle reduce ----
    const int warp = tid >> 5, lane = tid & 31;
    const int r = blockIdx.x * 16 + warp;
    const float4* __restrict__ row = reinterpret_cast<const float4*>(H + (size_t)r * DIM);
    const float4* __restrict__ p4  = reinterpret_cast<const float4*>(spsi);

    float acc = 0.f;
    #pragma unroll 8
    for (int j = lane; j < DIM / 4; j += 32) {
        const float4 h = row[j];
        const float4 p = p4[j];
        acc = fmaf(h.x, p.x, acc);
        acc = fmaf(h.y, p.y, acc);
        acc = fmaf(h.z, p.z, acc);
        acc = fmaf(h.w, p.w, acc);
    }
    #pragma unroll
    for (int o = 16; o > 0; o >>= 1) acc += __shfl_down_sync(0xffffffffu, acc, o);

    if (lane == 0) { rA[warp] = spsi[r] * acc; rB[warp] = acc * acc; }
    __syncthreads();

    if (tid == 0) {
        float e = 0.f, e2 = 0.f;
        #pragma unroll
        for (int w = 0; w < 16; w++) { e += rA[w]; e2 += rB[w]; }
        g_partE [blockIdx.x] = e;
        g_partE2[blockIdx.x] = e2;
        __threadfence();
        const int old = atomicAdd(&g_count, 1);
        s_is_last = (old == NBLK - 1);
    }
    __syncthreads();
    if (!s_is_last) return;
    __threadfence();

    // ---- finalize in the last block ----
    float n = 0.f;
    for (int i = tid; i < DIM; i += NTHR) n = fmaf(spsi[i], spsi[i], n);
    float e = 0.f, e2 = 0.f;
    if (tid < NBLK) { e = g_partE[tid]; e2 = g_partE2[tid]; }

    #pragma unroll
    for (int o = 16; o > 0; o >>= 1) {
        n  += __shfl_down_sync(0xffffffffu, n,  o);
        e  += __shfl_down_sync(0xffffffffu, e,  o);
        e2 += __shfl_down_sync(0xffffffffu, e2, o);
    }
    __syncthreads();   // rA/rB reuse
    if (lane == 0) { rA[warp] = n; rB[warp] = e; rC[warp] = e2; }
    __syncthreads();
    if (tid == 0) {
        float N = 0.f, E = 0.f, E2 = 0.f;
        #pragma unroll
        for (int w = 0; w < 16; w++) { N += rA[w]; E += rB[w]; E2 += rC[w]; }
        const float inv    = 1.f / N;
        const float energy = E * inv;
        out[0] = energy;
        out[1] = fmaxf(E2 * inv - energy * energy, 0.f);
        g_count = 0;                     // reset for next graph replay
    }
}

// ---------------- launch ----------------
extern "C" void kernel_launch(void* const* d_in, const int* in_sizes, int n_in,
                              void* d_out, int out_size) {
    const float* core0 = (const float*)d_in[0];   // (2, 8)
    const float* mid   = (const float*)d_in[1];   // (10, 8, 2, 8)
    const float* last  = (const float*)d_in[2];   // (8, 2)
    const float* H     = (const float*)d_in[3];   // (4096, 4096)
    float* out = (float*)d_out;

    vqe_fused_kernel<<<NBLK, NTHR>>>(core0, mid, last, H, out);
}

// round 16
// speedup vs baseline: 1.0114x; 1.0114x over previous
#include <cuda_runtime.h>
#include <cuda_bf16.h>

#define DIM   4096
#define NBLK  256          // 256 blocks * 16 warps = 4096 rows
#define NTHR  512

// ---------------- scratch (no allocations allowed) ----------------
__device__ float g_partE [NBLK];
__device__ float g_partE2[NBLK];
__device__ int   g_count = 0;

// Single fused kernel:
//  1) every block rebuilds psi[4096] in smem via MPS prefix/suffix split
//     psi[hi*64+lo] = sum_a L[hi][a] * R[lo][a]
//  2) 16 warps x 1 row each: acc = H[row] . psi  (one pass over H)
//     e_num  += psi[r]*acc ; e2_num += acc*acc   (H symmetric => <psi|H^2|psi> = |H psi|^2)
//  3) last block (atomic counter) reduces the 256 partials, computes norm from
//     its own psi copy (bitwise identical in all blocks), writes [energy, var],
//     resets counter.
__global__ __launch_bounds__(NTHR) void vqe_fused_kernel(
        const float* __restrict__ core0,   // (2,8)
        const float* __restrict__ mid,     // (10,8,2,8)
        const float* __restrict__ last,    // (8,2)
        const float* __restrict__ H,       // (4096,4096)
        float* __restrict__ out)
{
    __shared__ float sco[16 + 1280 + 16];        // core0 | mid | last
    __shared__ float LA[512], LB[512], RA[512], RB[512];
    __shared__ float spsi[DIM];                  // 16 KB
    __shared__ float rA[16], rB[16], rC[16];
    __shared__ int   s_is_last;

    const int tid = threadIdx.x;

    // ---- stage tiny cores into smem ----
    for (int i = tid; i < 16; i += NTHR) { sco[i] = core0[i]; sco[16 + 1280 + i] = last[i]; }
    for (int i = tid; i < 1280; i += NTHR) sco[16 + i] = mid[i];
    __syncthreads();
    const float* smid  = sco + 16;
    const float* slst  = sco + 16 + 1280;

    // ---- seed L^(0) (2 vectors = core0 rows), R^(0) (2 vectors from last) ----
    if (tid < 16) LA[tid] = sco[tid];                       // L0[s0*8+a] = core0[s0,a]
    if (tid >= 32 && tid < 48) {
        int t = tid - 32, p = t >> 3, a = t & 7;
        RA[p * 8 + a] = slst[a * 2 + p];                    // R0[p11][a] = last[a,p11]
    }
    __syncthreads();

    // ---- 5 doubling steps each side (L uses mid[0..4], R uses mid[9..5]) ----
    float *Lc = LA, *Ln = LB, *Rc = RA, *Rn = RB;
    int cnt = 2;
    for (int step = 0; step < 5; step++) {
        const int   tot = cnt * 16;                         // outputs per side
        const float* cl = smid + step * 128;
        const float* cr = smid + (9 - step) * 128;
        for (int idx = tid; idx < 2 * tot; idx += NTHR) {
            if (idx < tot) {                                // L: [s,p](b)
                const int b = idx & 7, sp = idx >> 3, p = sp & 1, s = sp >> 1;
                float sum = 0.f;
                #pragma unroll
                for (int a = 0; a < 8; a++)
                    sum = fmaf(Lc[s * 8 + a], cl[(a * 2 + p) * 8 + b], sum);
                Ln[idx] = sum;
            } else {                                        // R: [p,old](a), p = new MSB
                const int k = idx - tot;
                const int a = k & 7, v = k >> 3;
                const int p = (v >= cnt) ? 1 : 0;
                const int old = v - p * cnt;
                float sum = 0.f;
                #pragma unroll
                for (int b = 0; b < 8; b++)
                    sum = fmaf(cr[(a * 2 + p) * 8 + b], Rc[old * 8 + b], sum);
                Rn[k] = sum;
            }
        }
        __syncthreads();
        float* t;
        t = Lc; Lc = Ln; Ln = t;
        t = Rc; Rc = Rn; Rn = t;
        cnt <<= 1;
    }

    // ---- psi = outer contraction L[64][8] x R[64][8] ----
    for (int idx = tid; idx < DIM; idx += NTHR) {
        const int hi = idx >> 6, lo = idx & 63;
        float s = 0.f;
        #pragma unroll
        for (int a = 0; a < 8; a++)
            s = fmaf(Lc[hi * 8 + a], Rc[lo * 8 + a], s);
        spsi[idx] = s;
    }
    __syncthreads();

    // ---- matvec: one warp per row, float4 loads, warp-shuffle reduce ----
    const int warp = tid >> 5, lane = tid & 31;
    const int r = blockIdx.x * 16 + warp;
    const float4* __restrict__ row = reinterpret_cast<const float4*>(H + (size_t)r * DIM);
    const float4* __restrict__ p4  = reinterpret_cast<const float4*>(spsi);

    float acc = 0.f;
    #pragma unroll 8
    for (int j = lane; j < DIM / 4; j += 32) {
        const float4 h = row[j];
        const float4 p = p4[j];
        acc = fmaf(h.x, p.x, acc);
        acc = fmaf(h.y, p.y, acc);
        acc = fmaf(h.z, p.z, acc);
        acc = fmaf(h.w, p.w, acc);
    }
    #pragma unroll
    for (int o = 16; o > 0; o >>= 1) acc += __shfl_down_sync(0xffffffffu, acc, o);

    if (lane == 0) { rA[warp] = spsi[r] * acc; rB[warp] = acc * acc; }
    __syncthreads();

    if (tid == 0) {
        float e = 0.f, e2 = 0.f;
        #pragma unroll
        for (int w = 0; w < 16; w++) { e += rA[w]; e2 += rB[w]; }
        g_partE [blockIdx.x] = e;
        g_partE2[blockIdx.x] = e2;
        __threadfence();
        const int old = atomicAdd(&g_count, 1);
        s_is_last = (old == NBLK - 1);
    }
    __syncthreads();
    if (!s_is_last) return;
    __threadfence();

    // ---- finalize in the last block ----
    float n = 0.f;
    for (int i = tid; i < DIM; i += NTHR) n = fmaf(spsi[i], spsi[i], n);
    float e = 0.f, e2 = 0.f;
    if (tid < NBLK) { e = g_partE[tid]; e2 = g_partE2[tid]; }

    #pragma unroll
    for (int o = 16; o > 0; o >>= 1) {
        n  += __shfl_down_sync(0xffffffffu, n,  o);
        e  += __shfl_down_sync(0xffffffffu, e,  o);
        e2 += __shfl_down_sync(0xffffffffu, e2, o);
    }
    __syncthreads();   // rA/rB reuse
    if (lane == 0) { rA[warp] = n; rB[warp] = e; rC[warp] = e2; }
    __syncthreads();
    if (tid == 0) {
        float N = 0.f, E = 0.f, E2 = 0.f;
        #pragma unroll
        for (int w = 0; w < 16; w++) { N += rA[w]; E += rB[w]; E2 += rC[w]; }
        const float inv    = 1.f / N;
        const float energy = E * inv;
        out[0] = energy;
        out[1] = fmaxf(E2 * inv - energy * energy, 0.f);
        g_count = 0;                     // reset for next graph replay
    }
}

// ---------------- launch ----------------
extern "C" void kernel_launch(void* const* d_in, const int* in_sizes, int n_in,
                              void* d_out, int out_size) {
    const float* core0 = (const float*)d_in[0];   // (2, 8)
    const float* mid   = (const float*)d_in[1];   // (10, 8, 2, 8)
    const float* last  = (const float*)d_in[2];   // (8, 2)
    const float* H     = (const float*)d_in[3];   // (4096, 4096)
    float* out = (float*)d_out;

    vqe_fused_kernel<<<NBLK, NTHR>>>(core0, mid, last, H, out);
}

// round 17
// speedup vs baseline: 1.1533x; 1.1404x over previous
#include <cuda_runtime.h>
#include <cuda_bf16.h>

#define DIM   4096
#define NBLK  256          // 256 blocks * 16 warps = 4096 rows
#define NTHR  512

// ---------------- scratch (no allocations allowed) ----------------
__device__ float g_partE [NBLK];
__device__ float g_partE2[NBLK];
__device__ int   g_count = 0;

// Single fused kernel:
//  1) every block rebuilds psi[4096] in smem via MPS prefix/suffix split
//     psi[hi*64+lo] = sum_a L[hi][a] * R[lo][a]
//  2) 16 warps x 1 row each: acc = H[row] . psi  (one pass over H)
//     e_num  += psi[r]*acc ; e2_num += acc*acc   (H symmetric => <psi|H^2|psi> = |H psi|^2)
//  3) last block (atomic counter) reduces the 256 partials, computes norm from
//     its own psi copy (bitwise identical in all blocks), writes [energy, var],
//     resets counter.
__global__ __launch_bounds__(NTHR) void vqe_fused_kernel(
        const float* __restrict__ core0,   // (2,8)
        const float* __restrict__ mid,     // (10,8,2,8)
        const float* __restrict__ last,    // (8,2)
        const float* __restrict__ H,       // (4096,4096)
        float* __restrict__ out)
{
    __shared__ float sco[16 + 1280 + 16];        // core0 | mid | last
    __shared__ float LA[512], LB[512], RA[512], RB[512];
    __shared__ float spsi[DIM];                  // 16 KB
    __shared__ float rA[16], rB[16], rC[16];
    __shared__ int   s_is_last;

    const int tid = threadIdx.x;

    // ---- stage tiny cores into smem ----
    for (int i = tid; i < 16; i += NTHR) { sco[i] = core0[i]; sco[16 + 1280 + i] = last[i]; }
    for (int i = tid; i < 1280; i += NTHR) sco[16 + i] = mid[i];
    __syncthreads();
    const float* smid  = sco + 16;
    const float* slst  = sco + 16 + 1280;

    // ---- seed L^(0) (2 vectors = core0 rows), R^(0) (2 vectors from last) ----
    if (tid < 16) LA[tid] = sco[tid];                       // L0[s0*8+a] = core0[s0,a]
    if (tid >= 32 && tid < 48) {
        int t = tid - 32, p = t >> 3, a = t & 7;
        RA[p * 8 + a] = slst[a * 2 + p];                    // R0[p11][a] = last[a,p11]
    }
    __syncthreads();

    // ---- 5 doubling steps each side (L uses mid[0..4], R uses mid[9..5]) ----
    float *Lc = LA, *Ln = LB, *Rc = RA, *Rn = RB;
    int cnt = 2;
    for (int step = 0; step < 5; step++) {
        const int   tot = cnt * 16;                         // outputs per side
        const float* cl = smid + step * 128;
        const float* cr = smid + (9 - step) * 128;
        for (int idx = tid; idx < 2 * tot; idx += NTHR) {
            if (idx < tot) {                                // L: [s,p](b)
                const int b = idx & 7, sp = idx >> 3, p = sp & 1, s = sp >> 1;
                float sum = 0.f;
                #pragma unroll
                for (int a = 0; a < 8; a++)
                    sum = fmaf(Lc[s * 8 + a], cl[(a * 2 + p) * 8 + b], sum);
                Ln[idx] = sum;
            } else {                                        // R: [p,old](a), p = new MSB
                const int k = idx - tot;
                const int a = k & 7, v = k >> 3;
                const int p = (v >= cnt) ? 1 : 0;
                const int old = v - p * cnt;
                float sum = 0.f;
                #pragma unroll
                for (int b = 0; b < 8; b++)
                    sum = fmaf(cr[(a * 2 + p) * 8 + b], Rc[old * 8 + b], sum);
                Rn[k] = sum;
            }
        }
        __syncthreads();
        float* t;
        t = Lc; Lc = Ln; Ln = t;
        t = Rc; Rc = Rn; Rn = t;
        cnt <<= 1;
    }

    // ---- psi = outer contraction L[64][8] x R[64][8] ----
    for (int idx = tid; idx < DIM; idx += NTHR) {
        const int hi = idx >> 6, lo = idx & 63;
        float s = 0.f;
        #pragma unroll
        for (int a = 0; a < 8; a++)
            s = fmaf(Lc[hi * 8 + a], Rc[lo * 8 + a], s);
        spsi[idx] = s;
    }
    __syncthreads();

    // ---- matvec: one warp per row, float4 loads, warp-shuffle reduce ----
    const int warp = tid >> 5, lane = tid & 31;
    const int r = blockIdx.x * 16 + warp;
    const float4* __restrict__ row = reinterpret_cast<const float4*>(H + (size_t)r * DIM);
    const float4* __restrict__ p4  = reinterpret_cast<const float4*>(spsi);

    float acc = 0.f;
    #pragma unroll 8
    for (int j = lane; j < DIM / 4; j += 32) {
        const float4 h = row[j];
        const float4 p = p4[j];
        acc = fmaf(h.x, p.x, acc);
        acc = fmaf(h.y, p.y, acc);
        acc = fmaf(h.z, p.z, acc);
        acc = fmaf(h.w, p.w, acc);
    }
    #pragma unroll
    for (int o = 16; o > 0; o >>= 1) acc += __shfl_down_sync(0xffffffffu, acc, o);

    if (lane == 0) { rA[warp] = spsi[r] * acc; rB[warp] = acc * acc; }
    __syncthreads();

    if (tid == 0) {
        float e = 0.f, e2 = 0.f;
        #pragma unroll
        for (int w = 0; w < 16; w++) { e += rA[w]; e2 += rB[w]; }
        g_partE [blockIdx.x] = e;
        g_partE2[blockIdx.x] = e2;
        __threadfence();
        const int old = atomicAdd(&g_count, 1);
        s_is_last = (old == NBLK - 1);
    }
    __syncthreads();
    if (!s_is_last) return;
    __threadfence();

    // ---- finalize in the last block ----
    float n = 0.f;
    for (int i = tid; i < DIM; i += NTHR) n = fmaf(spsi[i], spsi[i], n);
    float e = 0.f, e2 = 0.f;
    if (tid < NBLK) { e = g_partE[tid]; e2 = g_partE2[tid]; }

    #pragma unroll
    for (int o = 16; o > 0; o >>= 1) {
        n  += __shfl_down_sync(0xffffffffu, n,  o);
        e  += __shfl_down_sync(0xffffffffu, e,  o);
        e2 += __shfl_down_sync(0xffffffffu, e2, o);
    }
    __syncthreads();   // rA/rB reuse
    if (lane == 0) { rA[warp] = n; rB[warp] = e; rC[warp] = e2; }
    __syncthreads();
    if (tid == 0) {
        float N = 0.f, E = 0.f, E2 = 0.f;
        #pragma unroll
        for (int w = 0; w < 16; w++) { N += rA[w]; E += rB[w]; E2 += rC[w]; }
        const float inv    = 1.f / N;
        const float energy = E * inv;
        out[0] = energy;
        out[1] = fmaxf(E2 * inv - energy * energy, 0.f);
        g_count = 0;                     // reset for next graph replay
    }
}

// ---------------- launch ----------------
extern "C" void kernel_launch(void* const* d_in, const int* in_sizes, int n_in,
                              void* d_out, int out_size) {
    const float* core0 = (const float*)d_in[0];   // (2, 8)
    const float* mid   = (const float*)d_in[1];   // (10, 8, 2, 8)
    const float* last  = (const float*)d_in[2];   // (8, 2)
    const float* H     = (const float*)d_in[3];   // (4096, 4096)
    float* out = (float*)d_out;

    vqe_fused_kernel<<<NBLK, NTHR>>>(core0, mid, last, H, out);
}